// round 1
// baseline (speedup 1.0000x reference)
#include <cuda_runtime.h>
#include <cuda_bf16.h>
#include <math.h>

// Problem constants
#define NN   50000
#define EE   800000
#define HID  128
#define SC   128
#define EIN  16
#define TT   5
#define NH   4
#define KK   4
#define INVAR 100
#define XDIM 484        // h_i(128) + h_j(128) + invar(100) + edge_feature(128)
#define XS   488        // padded row stride for x in shared
#define EPB  32         // edges per CTA
#define NPB  32         // nodes per CTA

// Accumulators (device globals: no allocation allowed)
__device__ float g_msg[(size_t)NN * HID];    // segment_sum(msg)
__device__ float g_zacc[(size_t)NN * 48];    // segment_sum(Z_agg)
__device__ float g_cnt[NN];                  // edge counts

__device__ __forceinline__ float silu_f(float x) {
    return x / (1.0f + __expf(-x));
}

__device__ __forceinline__ void red4(float* p, float x, float y, float z, float w) {
    asm volatile("red.global.add.v4.f32 [%0], {%1,%2,%3,%4};"
                 :: "l"(p), "f"(x), "f"(y), "f"(z), "f"(w) : "memory");
}

// Tiled GEMM helper: out[32][128] = act(A[32][Kdim] @ W[Kdim][128] + bias)
// 8 warps: warp -> 4 rows, lane -> 4 output cols (j0 = lane*4).
__device__ __forceinline__ void tile_gemm128(
    const float* A, int sA, int Kdim,
    const float* __restrict__ W, const float* __restrict__ bias,
    float* outS, int warp, int lane, bool act)
{
    float acc[4][4];
    #pragma unroll
    for (int i = 0; i < 4; i++)
        #pragma unroll
        for (int j = 0; j < 4; j++) acc[i][j] = 0.0f;

    const float* a0 = A + (warp * 4 + 0) * sA;
    const float* a1 = A + (warp * 4 + 1) * sA;
    const float* a2 = A + (warp * 4 + 2) * sA;
    const float* a3 = A + (warp * 4 + 3) * sA;
    const float* wp = W + lane * 4;

    #pragma unroll 4
    for (int k = 0; k < Kdim; k++) {
        float4 w = __ldg((const float4*)(wp + (size_t)k * 128));
        float b0 = a0[k], b1 = a1[k], b2 = a2[k], b3 = a3[k];
        acc[0][0] += b0 * w.x; acc[0][1] += b0 * w.y; acc[0][2] += b0 * w.z; acc[0][3] += b0 * w.w;
        acc[1][0] += b1 * w.x; acc[1][1] += b1 * w.y; acc[1][2] += b1 * w.z; acc[1][3] += b1 * w.w;
        acc[2][0] += b2 * w.x; acc[2][1] += b2 * w.y; acc[2][2] += b2 * w.z; acc[2][3] += b2 * w.w;
        acc[3][0] += b3 * w.x; acc[3][1] += b3 * w.y; acc[3][2] += b3 * w.z; acc[3][3] += b3 * w.w;
    }
    float4 bv = __ldg((const float4*)(bias + lane * 4));
    #pragma unroll
    for (int ee = 0; ee < 4; ee++) {
        float o0 = acc[ee][0] + bv.x;
        float o1 = acc[ee][1] + bv.y;
        float o2 = acc[ee][2] + bv.z;
        float o3 = acc[ee][3] + bv.w;
        if (act) { o0 = silu_f(o0); o1 = silu_f(o1); o2 = silu_f(o2); o3 = silu_f(o3); }
        float* o = outS + (warp * 4 + ee) * 128 + lane * 4;
        o[0] = o0; o[1] = o1; o[2] = o2; o[3] = o3;
    }
}

// ---------------------------------------------------------------------------
// Zero accumulators
// ---------------------------------------------------------------------------
__global__ void zero_kernel() {
    size_t idx = (size_t)blockIdx.x * blockDim.x + threadIdx.x;
    size_t stride = (size_t)gridDim.x * blockDim.x;
    for (size_t i = idx; i < (size_t)NN * HID; i += stride) g_msg[i] = 0.0f;
    for (size_t i = idx; i < (size_t)NN * 48; i += stride) g_zacc[i] = 0.0f;
    for (size_t i = idx; i < NN; i += stride) g_cnt[i] = 0.0f;
}

// ---------------------------------------------------------------------------
// Edge kernel: 32 edges per 256-thread CTA
// ---------------------------------------------------------------------------
__global__ void __launch_bounds__(256, 2) edge_kernel(
    const float* __restrict__ Z, const float* __restrict__ h,
    const int* __restrict__ ei,
    const float* __restrict__ edf, const float* __restrict__ edv,
    const float* __restrict__ We, const float* __restrict__ be,
    const float* __restrict__ Wm1, const float* __restrict__ bm1,
    const float* __restrict__ Wm2, const float* __restrict__ bm2,
    const float* __restrict__ Wv1, const float* __restrict__ bv1,
    const float* __restrict__ Wv2, const float* __restrict__ bv2)
{
    extern __shared__ float sm[];
    float* xs   = sm;               // 32 * 488 = 15616  (x, later basis in cols 0..79)
    float* zs   = sm + 15616;       // 32 * 64  = 2048   (Z_ij, layout d*20+t*4+h)
    float* h1   = sm + 17664;       // 32 * 128 = 4096
    float* h2   = sm + 21760;       // 32 * 128 = 4096   (msg)
    float* Wes  = sm + 25856;       // 2048
    float* edfs = sm + 27904;       // 512
    int*   ssrc = (int*)(sm + 28416); // 32
    int*   sdst = ssrc + 32;          // 32

    const int tid  = threadIdx.x;
    const int warp = tid >> 5;
    const int lane = tid & 31;
    const int e0   = blockIdx.x * EPB;

    // ---- Phase 0: stage inputs ----
    if (tid < EPB) {
        ssrc[tid] = ei[e0 + tid];
        sdst[tid] = ei[EE + e0 + tid];
    }
    for (int i = tid; i < EIN * 128; i += 256) Wes[i] = We[i];
    for (int i = tid; i < EPB * EIN; i += 256) edfs[i] = edf[(size_t)e0 * EIN + i];
    __syncthreads();

    // gather h: x[0:128] = h[dst] (h_i), x[128:256] = h[src] (h_j)
    for (int i = tid; i < EPB * 32; i += 256) {
        int e = i >> 5, c = i & 31;
        float4 vi = __ldg((const float4*)(h + (size_t)sdst[e] * 128 + c * 4));
        float4 vj = __ldg((const float4*)(h + (size_t)ssrc[e] * 128 + c * 4));
        *(float4*)(xs + e * XS + c * 4) = vi;
        *(float4*)(xs + e * XS + 128 + c * 4) = vj;
    }
    // Z_ij, t < 4: Z[dst] - Z[src]
    for (int i = tid; i < EPB * 48; i += 256) {
        int e = i / 48, r = i % 48;
        int d = r >> 4, q = r & 15;
        float v = __ldg(Z + (size_t)sdst[e] * 48 + r) - __ldg(Z + (size_t)ssrc[e] * 48 + r);
        zs[e * 64 + d * 20 + q] = v;
    }
    // Z_ij, t == 4: edge_distance_vec broadcast over heads
    for (int i = tid; i < EPB * 12; i += 256) {
        int e = i / 12, r = i % 12;
        int d = r >> 2, hh = r & 3;
        zs[e * 64 + d * 20 + 16 + hh] = __ldg(edv + (size_t)(e0 + e) * 3 + d);
    }
    __syncthreads();

    // ---- invariants + L2 normalize (one warp per 4 edges) ----
    for (int eloc = 0; eloc < 4; eloc++) {
        int e = warp * 4 + eloc;
        float v[4];
        float sq = 0.0f;
        #pragma unroll
        for (int u = 0; u < 4; u++) {
            int m = lane + u * 32;
            float val = 0.0f;
            if (m < INVAR) {
                int t = m / 20, rem = m % 20;
                int r2 = rem >> 2, hh = rem & 3;
                const float* z = zs + e * 64;
                val = z[0 * 20 + t * 4 + hh] * z[0 * 20 + r2 * 4 + hh]
                    + z[1 * 20 + t * 4 + hh] * z[1 * 20 + r2 * 4 + hh]
                    + z[2 * 20 + t * 4 + hh] * z[2 * 20 + r2 * 4 + hh];
            }
            v[u] = val;
            sq += val * val;
        }
        #pragma unroll
        for (int off = 16; off > 0; off >>= 1)
            sq += __shfl_xor_sync(0xffffffffu, sq, off);
        float inv = 1.0f / fmaxf(sqrtf(sq), 1e-12f);
        #pragma unroll
        for (int u = 0; u < 4; u++) {
            int m = lane + u * 32;
            if (m < INVAR) xs[e * XS + 256 + m] = v[u] * inv;
        }
    }

    // ---- edge_feature = edf @ We + be -> x[356:484] ----
    {
        float acc[4][4];
        #pragma unroll
        for (int i = 0; i < 4; i++)
            #pragma unroll
            for (int j = 0; j < 4; j++) acc[i][j] = 0.0f;
        #pragma unroll
        for (int k = 0; k < EIN; k++) {
            float4 w = *(const float4*)(Wes + k * 128 + lane * 4);
            #pragma unroll
            for (int ee = 0; ee < 4; ee++) {
                float a = edfs[(warp * 4 + ee) * EIN + k];
                acc[ee][0] += a * w.x; acc[ee][1] += a * w.y;
                acc[ee][2] += a * w.z; acc[ee][3] += a * w.w;
            }
        }
        float4 bv = __ldg((const float4*)(be + lane * 4));
        #pragma unroll
        for (int ee = 0; ee < 4; ee++) {
            float* o = xs + (warp * 4 + ee) * XS + 356 + lane * 4;
            o[0] = acc[ee][0] + bv.x; o[1] = acc[ee][1] + bv.y;
            o[2] = acc[ee][2] + bv.z; o[3] = acc[ee][3] + bv.w;
        }
    }
    __syncthreads();

    // ---- msg MLP + vec MLP ----
    tile_gemm128(xs, XS, XDIM, Wm1, bm1, h1, warp, lane, true);   // hid1
    __syncthreads();
    tile_gemm128(h1, 128, 128, Wm2, bm2, h2, warp, lane, true);   // msg
    __syncthreads();
    tile_gemm128(h2, 128, 128, Wv1, bv1, h1, warp, lane, true);   // vh
    __syncthreads();

    // basis = vh @ Wv2 + bv2  (N = 80), store into xs[e][0..79]
    if (lane < 20) {
        float acc[4][4];
        #pragma unroll
        for (int i = 0; i < 4; i++)
            #pragma unroll
            for (int j = 0; j < 4; j++) acc[i][j] = 0.0f;
        const float* a0 = h1 + (warp * 4 + 0) * 128;
        const float* a1 = h1 + (warp * 4 + 1) * 128;
        const float* a2 = h1 + (warp * 4 + 2) * 128;
        const float* a3 = h1 + (warp * 4 + 3) * 128;
        #pragma unroll 4
        for (int k = 0; k < 128; k++) {
            float4 w = __ldg((const float4*)(Wv2 + (size_t)k * 80 + lane * 4));
            float b0 = a0[k], b1 = a1[k], b2 = a2[k], b3 = a3[k];
            acc[0][0] += b0 * w.x; acc[0][1] += b0 * w.y; acc[0][2] += b0 * w.z; acc[0][3] += b0 * w.w;
            acc[1][0] += b1 * w.x; acc[1][1] += b1 * w.y; acc[1][2] += b1 * w.z; acc[1][3] += b1 * w.w;
            acc[2][0] += b2 * w.x; acc[2][1] += b2 * w.y; acc[2][2] += b2 * w.z; acc[2][3] += b2 * w.w;
            acc[3][0] += b3 * w.x; acc[3][1] += b3 * w.y; acc[3][2] += b3 * w.z; acc[3][3] += b3 * w.w;
        }
        float4 bv = __ldg((const float4*)(bv2 + lane * 4));
        #pragma unroll
        for (int ee = 0; ee < 4; ee++) {
            float* o = xs + (warp * 4 + ee) * XS + lane * 4;
            o[0] = acc[ee][0] + bv.x; o[1] = acc[ee][1] + bv.y;
            o[2] = acc[ee][2] + bv.z; o[3] = acc[ee][3] + bv.w;
        }
    }
    __syncthreads();

    // ---- Phase 5: scatter-reduce ----
    // msg sum
    for (int i = tid; i < EPB * 32; i += 256) {
        int e = i >> 5, c = i & 31;
        const float4 v = *(const float4*)(h2 + e * 128 + c * 4);
        red4(g_msg + (size_t)sdst[e] * 128 + c * 4, v.x, v.y, v.z, v.w);
    }
    // counts
    if (tid < EPB) atomicAdd(&g_cnt[sdst[tid]], 1.0f);
    // Z_agg[e][d][k][h] = sum_t Zij[d][t][h] * basis[t][k][h]
    for (int i = tid; i < EPB * 12; i += 256) {
        int e = i / 12, rr = i % 12;
        int d = rr >> 2, kk = rr & 3;
        const float* z  = zs + e * 64 + d * 20;     // z[t*4 + h]
        const float* bs = xs + e * XS + kk * 4;     // bs[t*16 + h]
        float o[4];
        #pragma unroll
        for (int hh = 0; hh < 4; hh++) {
            float s = 0.0f;
            #pragma unroll
            for (int t = 0; t < TT; t++)
                s += z[t * 4 + hh] * bs[t * 16 + hh];
            o[hh] = s;
        }
        red4(g_zacc + (size_t)sdst[e] * 48 + rr * 4, o[0], o[1], o[2], o[3]);
    }
}

// ---------------------------------------------------------------------------
// Node kernel: 32 nodes per 256-thread CTA
// out layout: [ Z_out : NN*48 floats ][ h_out : NN*128 floats ]
// ---------------------------------------------------------------------------
__global__ void __launch_bounds__(256, 2) node_kernel(
    const float* __restrict__ h,
    const float* __restrict__ Ws1, const float* __restrict__ bs1,
    const float* __restrict__ Ws2, const float* __restrict__ bs2,
    float* __restrict__ out)
{
    extern __shared__ float sm[];
    float* xn = sm;            // 32 * 256
    float* t1 = sm + 8192;     // 32 * 128

    const int tid  = threadIdx.x;
    const int warp = tid >> 5;
    const int lane = tid & 31;
    const int n0   = blockIdx.x * NPB;

    // load x = concat(h[n], msg_sum[n])
    for (int i = tid; i < NPB * 64; i += 256) {
        int v = i >> 6, c = i & 63;
        int n = n0 + v;
        int nc = n < NN ? n : (NN - 1);
        float4 val;
        if (c < 32) val = __ldg((const float4*)(h + (size_t)nc * 128 + c * 4));
        else        val = *(const float4*)(g_msg + (size_t)nc * 128 + (c - 32) * 4);
        *(float4*)(xn + v * 256 + c * 4) = val;
    }
    __syncthreads();

    tile_gemm128(xn, 256, 256, Ws1, bs1, t1, warp, lane, true);
    __syncthreads();

    // h_out = t1 @ Ws2 + bs2 (no activation), write to global
    {
        float acc[4][4];
        #pragma unroll
        for (int i = 0; i < 4; i++)
            #pragma unroll
            for (int j = 0; j < 4; j++) acc[i][j] = 0.0f;
        const float* a0 = t1 + (warp * 4 + 0) * 128;
        const float* a1 = t1 + (warp * 4 + 1) * 128;
        const float* a2 = t1 + (warp * 4 + 2) * 128;
        const float* a3 = t1 + (warp * 4 + 3) * 128;
        #pragma unroll 4
        for (int k = 0; k < 128; k++) {
            float4 w = __ldg((const float4*)(Ws2 + (size_t)k * 128 + lane * 4));
            float b0 = a0[k], b1 = a1[k], b2 = a2[k], b3 = a3[k];
            acc[0][0] += b0 * w.x; acc[0][1] += b0 * w.y; acc[0][2] += b0 * w.z; acc[0][3] += b0 * w.w;
            acc[1][0] += b1 * w.x; acc[1][1] += b1 * w.y; acc[1][2] += b1 * w.z; acc[1][3] += b1 * w.w;
            acc[2][0] += b2 * w.x; acc[2][1] += b2 * w.y; acc[2][2] += b2 * w.z; acc[2][3] += b2 * w.w;
            acc[3][0] += b3 * w.x; acc[3][1] += b3 * w.y; acc[3][2] += b3 * w.z; acc[3][3] += b3 * w.w;
        }
        float4 bv = __ldg((const float4*)(bs2 + lane * 4));
        #pragma unroll
        for (int ee = 0; ee < 4; ee++) {
            int n = n0 + warp * 4 + ee;
            if (n < NN) {
                float* o = out + (size_t)NN * 48 + (size_t)n * 128 + lane * 4;
                float4 r;
                r.x = acc[ee][0] + bv.x; r.y = acc[ee][1] + bv.y;
                r.z = acc[ee][2] + bv.z; r.w = acc[ee][3] + bv.w;
                *(float4*)o = r;
            }
        }
    }

    // Z_out = Z_acc / max(cnt, 1)
    for (int i = tid; i < NPB * 48; i += 256) {
        int v = i / 48, r = i % 48;
        int n = n0 + v;
        if (n < NN) {
            float c = fmaxf(g_cnt[n], 1.0f);
            out[(size_t)n * 48 + r] = g_zacc[(size_t)n * 48 + r] * (1.0f / c);
        }
    }
}

// ---------------------------------------------------------------------------
extern "C" void kernel_launch(void* const* d_in, const int* in_sizes, int n_in,
                              void* d_out, int out_size) {
    const float* Z   = (const float*)d_in[0];
    const float* h   = (const float*)d_in[1];
    const int*   ei  = (const int*)d_in[2];
    const float* edf = (const float*)d_in[3];
    const float* edv = (const float*)d_in[4];
    // d_in[5] = edge_distance (unused by the reference)
    const float* We  = (const float*)d_in[6];
    const float* be  = (const float*)d_in[7];
    const float* Wm1 = (const float*)d_in[8];
    const float* bm1 = (const float*)d_in[9];
    const float* Wm2 = (const float*)d_in[10];
    const float* bm2 = (const float*)d_in[11];
    const float* Wv1 = (const float*)d_in[12];
    const float* bv1 = (const float*)d_in[13];
    const float* Wv2 = (const float*)d_in[14];
    const float* bv2 = (const float*)d_in[15];
    const float* Ws1 = (const float*)d_in[16];
    const float* bs1 = (const float*)d_in[17];
    const float* Ws2 = (const float*)d_in[18];
    const float* bs2 = (const float*)d_in[19];
    float* out = (float*)d_out;

    const int edge_smem = 28480 * 4;   // 113,920 B
    const int node_smem = 12288 * 4;   // 49,152 B
    cudaFuncSetAttribute(edge_kernel, cudaFuncAttributeMaxDynamicSharedMemorySize, edge_smem);
    cudaFuncSetAttribute(node_kernel, cudaFuncAttributeMaxDynamicSharedMemorySize, node_smem);

    zero_kernel<<<1024, 256>>>();
    edge_kernel<<<EE / EPB, 256, edge_smem>>>(Z, h, ei, edf, edv,
                                              We, be, Wm1, bm1, Wm2, bm2,
                                              Wv1, bv1, Wv2, bv2);
    node_kernel<<<(NN + NPB - 1) / NPB, 256, node_smem>>>(h, Ws1, bs1, Ws2, bs2, out);
}